// round 7
// baseline (speedup 1.0000x reference)
#include <cuda_runtime.h>

#define N_  64
#define T_  4096
#define D_  128
#define CH  16
#define TCH (T_/CH)   // 256 timesteps per chunk; 32 per warp

// Scratch (no allocations allowed anywhere)
__device__ float g_partial[N_ * CH * D_];    // 512 KB
__device__ float g_chunksum[N_ * CH];        // 4 KB
__device__ int   g_ticket[N_];               // zero-init; finisher resets -> graph-replay safe

// ---------------------------------------------------------------------------
// Fused kernel: block (n, c) handles t in [c*TCH, (c+1)*TCH):
//   w = exp( (t<len[n]) * <key[t,n,:], q[n,:]> )   (no max-sub: |dot| << 88,
//   softmax cancels any shift exactly)
//   acc[d] += w * value[t,n,d] ;  ws += w
// Batch of 2 timesteps per iteration (4x LDG.128 front-batch) -- keeps regs
// <= 32 so 8 CTAs/SM stay resident (occupancy is the proven lever here) and
// keeps the per-CTA front-batched LDG count low to reduce cross-CTA L1tex
// queue contention (multi-CTA finish spread).
// Last block per n reduces the 16 partials and normalizes. All sums in fixed
// index order -> deterministic.
// ---------------------------------------------------------------------------
__global__ void __launch_bounds__(256) fused_attn_kernel(
    const float* __restrict__ q,
    const float* __restrict__ key,
    const float* __restrict__ value,
    const int* __restrict__ slen,          // int32 on device (JAX x64 off)
    float* __restrict__ out_ctx,
    float* __restrict__ mask_out)
{
    const int n    = blockIdx.x;           // fast index -> concurrent blocks
    const int c    = blockIdx.y;           //   span all n for one t-window
    const int lane = threadIdx.x & 31;
    const int wp   = threadIdx.x >> 5;
    const int len  = slen[n];

    // Coalesced mask write: 1KB per block
    {
        const int t = c * TCH + threadIdx.x;
        mask_out[(size_t)n * T_ + t] = (t < len) ? 1.0f : 0.0f;
    }

    const float4 qv = reinterpret_cast<const float4*>(q + (size_t)n * D_)[lane];
    const float4* __restrict__ k4 = reinterpret_cast<const float4*>(key);
    const float4* __restrict__ v4 = reinterpret_cast<const float4*>(value);

    const size_t strideT = (size_t)N_ * (D_ / 4);            // per-t stride (float4)
    const int    tbase   = c * TCH + wp * 32;                // this warp's first t
    const size_t idx0    = ((size_t)tbase * N_ + n) * (D_ / 4) + lane;

    float4 acc = make_float4(0.f, 0.f, 0.f, 0.f);
    float  ws  = 0.0f;

#pragma unroll
    for (int i = 0; i < 32; i += 2) {
        const size_t o0 = idx0 + (size_t)(i + 0) * strideT;
        const size_t o1 = idx0 + (size_t)(i + 1) * strideT;
        const float4 kv0 = k4[o0];
        const float4 kv1 = k4[o1];
        const float4 vv0 = v4[o0];
        const float4 vv1 = v4[o1];

        float p0 = kv0.x*qv.x + kv0.y*qv.y + kv0.z*qv.z + kv0.w*qv.w;
        float p1 = kv1.x*qv.x + kv1.y*qv.y + kv1.z*qv.z + kv1.w*qv.w;

#pragma unroll
        for (int s = 16; s > 0; s >>= 1) {
            p0 += __shfl_xor_sync(0xffffffffu, p0, s);
            p1 += __shfl_xor_sync(0xffffffffu, p1, s);
        }

        const float w0 = __expf((tbase + i + 0 < len) ? p0 : 0.0f);
        const float w1 = __expf((tbase + i + 1 < len) ? p1 : 0.0f);
        ws += w0;  ws += w1;
        acc.x += w0*vv0.x;  acc.y += w0*vv0.y;
        acc.z += w0*vv0.z;  acc.w += w0*vv0.w;
        acc.x += w1*vv1.x;  acc.y += w1*vv1.y;
        acc.z += w1*vv1.z;  acc.w += w1*vv1.w;
    }

    // Cross-warp reduce (fixed order -> deterministic)
    __shared__ float4 red[8][32];
    __shared__ float  wsum[8];
    __shared__ int    isLast;
    red[wp][lane] = acc;
    if (lane == 0) wsum[wp] = ws;
    __syncthreads();

    if (wp == 0) {
        float4 s = red[0][lane];
#pragma unroll
        for (int k = 1; k < 8; k++) {
            const float4 r = red[k][lane];
            s.x += r.x;  s.y += r.y;  s.z += r.z;  s.w += r.w;
        }
        reinterpret_cast<float4*>(g_partial + ((size_t)n * CH + c) * D_)[lane] = s;
        if (lane == 0) {
            float t = 0.0f;
#pragma unroll
            for (int k = 0; k < 8; k++) t += wsum[k];
            g_chunksum[n * CH + c] = t;
        }
        __threadfence();   // make this warp's partial/chunksum globally visible
    }
    __syncthreads();

    // Completion ticket: last block for this n does the final reduce.
    if (threadIdx.x == 0)
        isLast = (atomicAdd(&g_ticket[n], 1) == CH - 1) ? 1 : 0;
    __syncthreads();

    if (isLast) {
        if (threadIdx.x < D_) {
            const int d = threadIdx.x;
            float rs = 0.0f;
#pragma unroll
            for (int k = 0; k < CH; k++)
                rs += __ldcg(&g_chunksum[n * CH + k]);      // L1-bypass: other CTAs' data
            float s = 0.0f;
#pragma unroll
            for (int k = 0; k < CH; k++)
                s += __ldcg(&g_partial[((size_t)n * CH + k) * D_ + d]);
            out_ctx[(size_t)n * D_ + d] = s / rs;
        }
        if (threadIdx.x == 0) g_ticket[n] = 0;   // reset for next replay
    }
}

// ---------------------------------------------------------------------------
extern "C" void kernel_launch(void* const* d_in, const int* in_sizes, int n_in,
                              void* d_out, int out_size)
{
    const float* query = (const float*)d_in[0];
    const float* key   = (const float*)d_in[1];
    const float* value = (const float*)d_in[2];
    const int*   slen  = (const int*)d_in[3];   // int32 on device (JAX x64 off)

    float* out_ctx  = (float*)d_out;           // (N, D)
    float* out_mask = (float*)d_out + N_ * D_; // (N, T)

    dim3 g(N_, CH);   // n fastest -> concurrent CTAs read contiguous windows
    fused_attn_kernel<<<g, 256>>>(query, key, value, slen, out_ctx, out_mask);
}

// round 8
// speedup vs baseline: 1.2388x; 1.2388x over previous
#include <cuda_runtime.h>

#define N_  64
#define T_  4096
#define D_  128
#define CH  16
#define TCH (T_/CH)   // 256 timesteps per chunk; 32 per warp

// Scratch (no allocations allowed anywhere)
__device__ float g_partial[N_ * CH * D_];    // 512 KB
__device__ float g_chunksum[N_ * CH];        // 4 KB
__device__ int   g_ticket[N_];               // zero-init; finisher resets -> graph-replay safe

// ---------------------------------------------------------------------------
// Fused kernel (R4 configuration -- proven optimum):
// block (n, c) over t in [c*TCH, (c+1)*TCH):
//   w = exp( (t<len[n]) * <key[t,n,:], q[n,:]> )   (no max-sub needed:
//   |dot| << 88 fp32 exp range; softmax cancels shifts exactly)
//   acc[d] += w * value[t,n,d] ;  ws += w
// Batch-4 front loads (8x LDG.128 in flight), serialized per-t butterflies,
// 32 regs -> 8 CTAs/SM. launch_bounds(256,8) pins the 32-reg budget.
// Last block per n reduces the 16 partials and normalizes. Deterministic:
// every sum is taken in fixed index order regardless of arrival order.
// ---------------------------------------------------------------------------
__global__ void __launch_bounds__(256, 8) fused_attn_kernel(
    const float* __restrict__ q,
    const float* __restrict__ key,
    const float* __restrict__ value,
    const int* __restrict__ slen,          // int32 on device (JAX x64 off)
    float* __restrict__ out_ctx,
    float* __restrict__ mask_out)
{
    const int n    = blockIdx.x;           // fast index -> concurrent blocks
    const int c    = blockIdx.y;           //   span all n for one t-window
    const int lane = threadIdx.x & 31;
    const int wp   = threadIdx.x >> 5;
    const int len  = slen[n];

    // Coalesced mask write: 1KB per block
    {
        const int t = c * TCH + threadIdx.x;
        mask_out[(size_t)n * T_ + t] = (t < len) ? 1.0f : 0.0f;
    }

    const float4 qv = reinterpret_cast<const float4*>(q + (size_t)n * D_)[lane];
    const float4* __restrict__ k4 = reinterpret_cast<const float4*>(key);
    const float4* __restrict__ v4 = reinterpret_cast<const float4*>(value);

    const size_t strideT = (size_t)N_ * (D_ / 4);            // per-t stride (float4)
    const int    tbase   = c * TCH + wp * 32;                // this warp's first t
    const size_t idx0    = ((size_t)tbase * N_ + n) * (D_ / 4) + lane;

    float4 acc = make_float4(0.f, 0.f, 0.f, 0.f);
    float  ws  = 0.0f;

#pragma unroll
    for (int i = 0; i < 32; i += 4) {
        float4 kv[4], vv[4];
#pragma unroll
        for (int j = 0; j < 4; j++) {
            const size_t o = idx0 + (size_t)(i + j) * strideT;
            kv[j] = k4[o];
            vv[j] = v4[o];
        }
#pragma unroll
        for (int j = 0; j < 4; j++) {
            float p = kv[j].x * qv.x + kv[j].y * qv.y
                    + kv[j].z * qv.z + kv[j].w * qv.w;
            p += __shfl_xor_sync(0xffffffffu, p, 16);
            p += __shfl_xor_sync(0xffffffffu, p, 8);
            p += __shfl_xor_sync(0xffffffffu, p, 4);
            p += __shfl_xor_sync(0xffffffffu, p, 2);
            p += __shfl_xor_sync(0xffffffffu, p, 1);       // all lanes hold dot
            const float m = (tbase + i + j < len) ? 1.0f : 0.0f;
            const float w = __expf(m * p);                 // multiplicative mask
            ws += w;
            acc.x += w * vv[j].x;  acc.y += w * vv[j].y;
            acc.z += w * vv[j].z;  acc.w += w * vv[j].w;
        }
    }

    // Cross-warp reduce (fixed order -> deterministic)
    __shared__ float4 red[8][32];
    __shared__ float  wsum[8];
    __shared__ int    isLast;
    red[wp][lane] = acc;
    if (lane == 0) wsum[wp] = ws;
    __syncthreads();

    if (wp == 0) {
        float4 s = red[0][lane];
#pragma unroll
        for (int k = 1; k < 8; k++) {
            const float4 r = red[k][lane];
            s.x += r.x;  s.y += r.y;  s.z += r.z;  s.w += r.w;
        }
        reinterpret_cast<float4*>(g_partial + ((size_t)n * CH + c) * D_)[lane] = s;
        if (lane == 0) {
            float t = 0.0f;
#pragma unroll
            for (int k = 0; k < 8; k++) t += wsum[k];
            g_chunksum[n * CH + c] = t;
        }
        __threadfence();   // make this warp's partial/chunksum globally visible
    }
    __syncthreads();

    // Completion ticket: last block for this n does the final reduce.
    if (threadIdx.x == 0)
        isLast = (atomicAdd(&g_ticket[n], 1) == CH - 1) ? 1 : 0;
    __syncthreads();

    if (isLast) {
        if (threadIdx.x < D_) {
            const int d = threadIdx.x;
            float rs = 0.0f;
#pragma unroll
            for (int k = 0; k < CH; k++)
                rs += __ldcg(&g_chunksum[n * CH + k]);      // L1-bypass: other CTAs' data
            float s = 0.0f;
#pragma unroll
            for (int k = 0; k < CH; k++)
                s += __ldcg(&g_partial[((size_t)n * CH + k) * D_ + d]);
            out_ctx[(size_t)n * D_ + d] = s / rs;
        }
        if (threadIdx.x == 0) g_ticket[n] = 0;   // reset for next replay
    }
}

// ---------------------------------------------------------------------------
extern "C" void kernel_launch(void* const* d_in, const int* in_sizes, int n_in,
                              void* d_out, int out_size)
{
    const float* query = (const float*)d_in[0];
    const float* key   = (const float*)d_in[1];
    const float* value = (const float*)d_in[2];
    const int*   slen  = (const int*)d_in[3];   // int32 on device (JAX x64 off)

    float* out_ctx  = (float*)d_out;           // (N, D)
    float* out_mask = (float*)d_out + N_ * D_; // (N, T)

    dim3 g(N_, CH);   // n fastest -> concurrent CTAs read contiguous windows
    fused_attn_kernel<<<g, 256>>>(query, key, value, slen, out_ctx, out_mask);
}